// round 15
// baseline (speedup 1.0000x reference)
#include <cuda_runtime.h>
#include <cuda_fp16.h>
#include <cstdint>
#include <math.h>

// ---------------- Problem constants ----------------
#define BDIM   64
#define NNODES 1024
#define UDIM   64
#define NCOLS  4224          // 66 features * 64 batch
#define NM     6             // slots: 0=X0(pass1), 1..4 diffusion, 5=X0(pass2)
#define XTSZ   (NCOLS * NNODES)

// Diffusion GEMM tiling (fp16 single term), 4-stage pipeline
#define MT 128
#define NT 128
#define KC 32
#define NCHUNK 32
#define NSTAGE 4
#define ROWB 80
#define REG_BYTES (128 * ROWB)        // 10240
#define OFF_A  0
#define OFF_B  (1 * REG_BYTES)
#define STAGE_BYTES (2 * REG_BYTES)   // 20480
#define DSMEM_BYTES (NSTAGE * STAGE_BYTES)   // 81920 (>= epilogue 68096)

// ---------------- Device scratch ----------------
__device__ __align__(256) __half g_XT[NM][XTSZ];
__device__ __align__(256) __half g_S16[2][1024 * 1024];
__device__ __align__(256) __half g_Wo16[330 * 128];
__device__ __align__(256) __half g_Wu16[330 * 64];
__device__ __align__(256) float g_u[BDIM * NNODES * UDIM];

// ---------------- helpers ----------------
__device__ __forceinline__ uint32_t smem_u32(const void* p) {
    uint32_t a;
    asm("{ .reg .u64 t; cvta.to.shared.u64 t, %1; cvt.u32.u64 %0, t; }" : "=r"(a) : "l"(p));
    return a;
}
__device__ __forceinline__ void cp16(uint32_t saddr, const void* gaddr) {
    asm volatile("cp.async.cg.shared.global [%0], [%1], 16;" :: "r"(saddr), "l"(gaddr));
}
__device__ __forceinline__ void cp16z(uint32_t saddr, const void* gaddr, uint32_t srcsize) {
    asm volatile("cp.async.cg.shared.global [%0], [%1], 16, %2;"
                 :: "r"(saddr), "l"(gaddr), "r"(srcsize));
}
// tail-aware pipeline wait: guarantee group c is complete given how many
// newer groups can still be in flight (rem = groups issued after c).
__device__ __forceinline__ void pipe_wait(int rem) {
    if (rem >= 2)      asm volatile("cp.async.wait_group 2;" ::: "memory");
    else if (rem == 1) asm volatile("cp.async.wait_group 1;" ::: "memory");
    else               asm volatile("cp.async.wait_group 0;" ::: "memory");
}
__device__ __forceinline__ void ldmx4a(uint32_t* r, uint32_t addr) {
    asm volatile("ldmatrix.sync.aligned.m8n8.x4.shared.b16 {%0,%1,%2,%3}, [%4];"
                 : "=r"(r[0]), "=r"(r[1]), "=r"(r[2]), "=r"(r[3]) : "r"(addr));
}
__device__ __forceinline__ void ldmx4t(uint32_t* r, uint32_t addr) {
    asm volatile("ldmatrix.sync.aligned.m8n8.x4.trans.shared.b16 {%0,%1,%2,%3}, [%4];"
                 : "=r"(r[0]), "=r"(r[1]), "=r"(r[2]), "=r"(r[3]) : "r"(addr));
}
__device__ __forceinline__ void mmaf16(float* c, const uint32_t* a, uint32_t b0, uint32_t b1) {
    asm volatile(
        "mma.sync.aligned.m16n8k16.row.col.f32.f16.f16.f32 "
        "{%0,%1,%2,%3}, {%4,%5,%6,%7}, {%8,%9}, {%0,%1,%2,%3};"
        : "+f"(c[0]), "+f"(c[1]), "+f"(c[2]), "+f"(c[3])
        : "r"(a[0]), "r"(a[1]), "r"(a[2]), "r"(a[3]), "r"(b0), "r"(b1));
}

// ============================================================================
// fused preprocessing: S -> fp16, W -> fp16, input rows -> slots 0 & 5
// ============================================================================
#define PRE_TOTAL (2097152 + 63360 + 131072)
__global__ void pre_kernel(const float* __restrict__ S0, const float* __restrict__ S1,
                           const float* __restrict__ Wo, const float* __restrict__ Wu,
                           const float* __restrict__ inp) {
    int idx = blockIdx.x * 256 + threadIdx.x;
    if (idx < 2097152) {
        int z = idx >> 20;
        int e = idx & 1048575;
        g_S16[z][e] = __float2half((z ? S1 : S0)[e]);
    } else if (idx < 2097152 + 63360) {
        int e = idx - 2097152;
        if (e < 42240) g_Wo16[e] = __float2half(Wo[e]);
        else           g_Wu16[e - 42240] = __float2half(Wu[e - 42240]);
    } else if (idx < PRE_TOTAL) {
        int e = idx - (2097152 + 63360);
        int c = e >> 10, i = e & 1023;
        int f = c >> 6, b = c & 63;
        __half h = __float2half(inp[b * 2048 + i * 2 + f]);
        g_XT[0][c * 1024 + i] = h;
        g_XT[5][c * 1024 + i] = h;
    }
}

// hidden rows from hx (pass 1) via smem transpose
__global__ __launch_bounds__(256)
void build_h_kernel(const float* __restrict__ hsrc) {
    __shared__ float T[64][65];
    const int i0 = blockIdx.x * 64;
    const int b  = blockIdx.y;
    const int tid = threadIdx.x;
    {
        const int u = tid & 63;
        const int iib = tid >> 6;
#pragma unroll
        for (int w = 0; w < 16; ++w) {
            const int ii = iib + w * 4;
            T[u][ii] = hsrc[(size_t)b * 65536 + (size_t)(i0 + ii) * 64 + u];
        }
    }
    __syncthreads();
    {
        const int ii = tid & 63;
        const int ub = tid >> 6;
#pragma unroll
        for (int w = 0; w < 16; ++w) {
            const int u = ub + w * 4;
            g_XT[0][(size_t)((u + 2) * 64 + b) * 1024 + i0 + ii] = __float2half(T[u][ii]);
        }
    }
}

// ============================================================================
// fp16 mma.sync diffusion GEMM: C = S[z] @ X[mi]  (CHEB: 2C - X0)
// grid (33, 8, 2), 256 threads. 4-stage cp.async pipeline, 1 barrier/chunk.
// ============================================================================
template <bool CHEB>
__global__ __launch_bounds__(256)
void gemm_mma(int inBase, int inStride, int outBase, int x0Idx) {
    const int z = blockIdx.z;
    const int it = blockIdx.y, jt = blockIdx.x;
    const int mi_idx = inBase + z * inStride;
    const int mo = outBase + 2 * z;

    const __half* __restrict__ Am = g_S16[z];
    const __half* __restrict__ Bm = g_XT[mi_idx];
    __half* __restrict__ Cm = g_XT[mo];
    const __half* __restrict__ X0 = g_XT[x0Idx];

    extern __shared__ char sm[];
    const uint32_t sb0 = smem_u32(sm);

    const int tid = threadIdx.x;
    const int warp = tid >> 5;
    const int lane = tid & 31;
    const int wm = warp >> 2;
    const int wn = warp & 3;

    const size_t arow0 = (size_t)(it * MT) * 1024;
    const size_t brow0 = (size_t)(jt * NT) * 1024;

    const uint32_t a_lm = (uint32_t)((lane & 15) * ROWB + ((lane >> 4) << 4));
    const uint32_t b_lm = (uint32_t)((((lane >> 4) << 3) + (lane & 7)) * ROWB +
                                     (((lane >> 3) & 1) << 4));

    float acc[4][4][4];
#pragma unroll
    for (int i = 0; i < 4; i++)
#pragma unroll
        for (int j = 0; j < 4; j++)
#pragma unroll
            for (int r = 0; r < 4; r++) acc[i][j][r] = 0.f;

    auto issue = [&](int c) {
        const int buf = c & (NSTAGE - 1);
        const int k0 = c * KC;
        const uint32_t sbase = sb0 + buf * STAGE_BYTES;
#pragma unroll
        for (int q = 0; q < 4; q++) {
            int idx = tid + q * 256;
            int region = idx >> 9;             // 0..1
            int row = (idx >> 2) & 127;
            int seg = idx & 3;
            const __half* gp = region ? (Bm + brow0) : (Am + arow0);
            gp += (size_t)row * 1024 + k0 + seg * 8;
            cp16(sbase + region * REG_BYTES + row * ROWB + seg * 16, gp);
        }
        asm volatile("cp.async.commit_group;" ::: "memory");
    };

    issue(0); issue(1); issue(2);

    for (int c = 0; c < NCHUNK; ++c) {
        pipe_wait(NCHUNK - 1 - c);     // group c guaranteed complete
        __syncthreads();
        if (c + NSTAGE - 1 < NCHUNK) issue(c + NSTAGE - 1);

        const uint32_t sbase = sb0 + (c & (NSTAGE - 1)) * STAGE_BYTES;
        const uint32_t aB = sbase + a_lm + (uint32_t)(wm * 64) * ROWB;
        const uint32_t bB = sbase + b_lm + (uint32_t)(wn * 32) * ROWB;

        // preload ALL B fragments (both k-steps)
        uint32_t bF[2][2][4];
#pragma unroll
        for (int s = 0; s < 2; ++s) {
            const uint32_t ks = (uint32_t)(s << 5);
#pragma unroll
            for (int p = 0; p < 2; ++p)
                ldmx4a(bF[s][p], bB + OFF_B + (uint32_t)(p * 16) * ROWB + ks);
        }
        // A ping-pong
        uint32_t aF[2][4];
        ldmx4a(aF[0], aB + OFF_A);
#pragma unroll
        for (int g = 0; g < 8; ++g) {
            const int s = g >> 2, mi = g & 3;
            const int cur = g & 1;
            if (g < 7) {
                const int g2 = g + 1;
                const uint32_t ao = (uint32_t)((g2 & 3) * 16) * ROWB +
                                    (uint32_t)((g2 >> 2) << 5);
                ldmx4a(aF[cur ^ 1], aB + OFF_A + ao);
            }
#pragma unroll
            for (int nj = 0; nj < 4; ++nj) {
                const int p = nj >> 1, h = (nj & 1) << 1;
                mmaf16(acc[mi][nj], aF[cur], bF[s][p][h], bF[s][p][h + 1]);
            }
        }
    }
    __syncthreads();   // protect smem reuse as epilogue buffer

    // epilogue: stride-133 smem transpose; scalar stores (odd stride, 8B traps)
    float* Csm = (float*)sm;
    const int gid = lane >> 2;
    const int tig = lane & 3;
#pragma unroll
    for (int mi = 0; mi < 4; ++mi) {
#pragma unroll
        for (int nj = 0; nj < 4; ++nj) {
            const int r0 = wm * 64 + mi * 16 + gid;
            const int n = wn * 32 + nj * 8 + 2 * tig;
            Csm[r0 * 133 + n]           = acc[mi][nj][0];
            Csm[r0 * 133 + n + 1]       = acc[mi][nj][1];
            Csm[(r0 + 8) * 133 + n]     = acc[mi][nj][2];
            Csm[(r0 + 8) * 133 + n + 1] = acc[mi][nj][3];
        }
    }
    __syncthreads();

#pragma unroll 1
    for (int iter = 0; iter < 16; ++iter) {
        const int j = iter * 8 + warp;
        const size_t jg = (size_t)(jt * NT + j);
#pragma unroll
        for (int q = 0; q < 4; ++q) {
            const int i = lane + q * 32;
            const size_t ig = (size_t)(it * MT) + i;
            float y = Csm[i * 133 + j];
            if (CHEB)
                y = 2.f * y - __half2float(X0[jg * 1024 + ig]);
            Cm[jg * 1024 + ig] = __float2half(y);
        }
    }
}

// ============================================================================
// Tensor-core projection (fp16 single-term). K=330 padded to 336.
// 4-stage pipeline, 1 barrier/chunk, tail-aware waits.
// IS_P1: r -> XT slot 5 hidden rows fused, u -> g_u.
// else : c = tanh(.), out = u*hx + (1-u)*c.
// ============================================================================
template <int OUT, int NTILE, int PX, int PW, int PY, bool IS_P1>
__global__ __launch_bounds__(256)
void proj_mma(const __half* __restrict__ Wm, const float* __restrict__ bias,
              const float* __restrict__ hx, float* __restrict__ outp, int x0slot) {
    constexpr int XSEG = NTILE / 8;
    constexpr int WSEG = OUT / 8;
    constexpr int OFF_X = 0;
    constexpr int OFF_W = 16 * PX;
    constexpr int STAGE = 16 * PX + 16 * PW;
    constexpr int TOTAL = 2 * NTILE + 2 * OUT;
    constexpr int NQ = (TOTAL + 255) / 256;
    constexpr int NCK = 21;
    constexpr int WN_CNT = NTILE / 32;

    const int n0 = blockIdx.x * NTILE;
    const int b  = blockIdx.y;

    extern __shared__ char sm[];
    const uint32_t sb0 = smem_u32(sm);

    const int tid = threadIdx.x;
    const int warp = tid >> 5;
    const int lane = tid & 31;
    const int wm = warp / WN_CNT;
    const int wn = warp % WN_CNT;

    const uint32_t a_lmT = (uint32_t)(((lane & 7) + ((lane >> 4) & 1) * 8) * PW +
                                      (((lane >> 3) & 1) << 4));
    const uint32_t b_lmT = (uint32_t)(((lane & 7) + ((lane >> 3) & 1) * 8) * PX +
                                      ((lane >> 4) << 4));

    float acc[4][4][4];
#pragma unroll
    for (int i = 0; i < 4; i++)
#pragma unroll
        for (int j = 0; j < 4; j++)
#pragma unroll
            for (int r = 0; r < 4; r++) acc[i][j][r] = 0.f;

    const __half* X0 = &g_XT[0][0];

    auto issue = [&](int c) {
        const uint32_t sbase = sb0 + (c & 3) * STAGE;
        const int k0 = c * 16;
#pragma unroll
        for (int q = 0; q < NQ; q++) {
            int idx = tid + q * 256;
            if (idx >= TOTAL) break;
            if (idx < 2 * NTILE) {
                const int row = idx / XSEG, seg = idx % XSEG;
                const int k = k0 + row;
                const uint32_t sz = (k < 330) ? 16u : 0u;
                const int kk = (k < 330) ? k : 0;
                const int f = kk / 5, m = kk - f * 5;
                const int mslot = (m == 0) ? x0slot : m;
                const __half* src = X0 + (size_t)mslot * XTSZ +
                                    (size_t)(f * 64 + b) * 1024 + n0 + seg * 8;
                cp16z(sbase + OFF_X + row * PX + seg * 16, src, sz);
            } else {
                const int li = idx - 2 * NTILE;
                const int row = li / WSEG, seg = li % WSEG;
                const int k = k0 + row;
                const uint32_t sz = (k < 330) ? 16u : 0u;
                const int kk = (k < 330) ? k : 0;
                cp16z(sbase + OFF_W + row * PW + seg * 16, Wm + kk * OUT + seg * 8, sz);
            }
        }
        asm volatile("cp.async.commit_group;" ::: "memory");
    };

    issue(0); issue(1); issue(2);

    for (int c = 0; c < NCK; ++c) {
        pipe_wait(NCK - 1 - c);        // group c guaranteed complete
        __syncthreads();
        if (c + 3 < NCK) issue(c + 3);

        const uint32_t sbase = sb0 + (c & 3) * STAGE;
        uint32_t bF[2][4];
#pragma unroll
        for (int p = 0; p < 2; ++p)
            ldmx4t(bF[p], sbase + OFF_X + b_lmT + (uint32_t)((wn * 32 + p * 16) * 2));
#pragma unroll
        for (int mi = 0; mi < 4; ++mi) {
            uint32_t aw[4];
            ldmx4t(aw, sbase + OFF_W + a_lmT + (uint32_t)((wm * 64 + mi * 16) * 2));
#pragma unroll
            for (int nj = 0; nj < 4; ++nj) {
                const int p = nj >> 1, h = (nj & 1) << 1;
                mmaf16(acc[mi][nj], aw, bF[p][h], bF[p][h + 1]);
            }
        }
    }
    __syncthreads();   // protect smem reuse as epilogue buffer

    // stage Y^T[o][n] in smem (odd pitch PY; scalar stores)
    float* Ysm = (float*)sm;
    const int gid = lane >> 2;
    const int tig = lane & 3;
#pragma unroll
    for (int mi = 0; mi < 4; ++mi) {
#pragma unroll
        for (int nj = 0; nj < 4; ++nj) {
            const int o0 = wm * 64 + mi * 16 + gid;
            const int n = wn * 32 + nj * 8 + 2 * tig;
            Ysm[o0 * PY + n]           = acc[mi][nj][0];
            Ysm[o0 * PY + n + 1]       = acc[mi][nj][1];
            Ysm[(o0 + 8) * PY + n]     = acc[mi][nj][2];
            Ysm[(o0 + 8) * PY + n + 1] = acc[mi][nj][3];
        }
    }

    if (IS_P1) {
        float* Hsm = (float*)(sm + OUT * PY * 4);
        {
            const int o = tid & 63;
            const int ng = tid >> 6;
#pragma unroll
            for (int w = 0; w < NTILE / 4; ++w) {
                const int n = ng + w * 4;
                Hsm[n * 65 + o] = hx[(size_t)b * 65536 + (size_t)(n0 + n) * 64 + o];
            }
        }
        __syncthreads();
        {   // rh = sigmoid(Y + b0) * hx -> XT slot 5 (n-coalesced)
            const int n = tid & 127;
            const int og = tid >> 7;
#pragma unroll 1
            for (int ow = 0; ow < 32; ++ow) {
                const int o = og * 32 + ow;
                const float r = 1.f / (1.f + expf(-(Ysm[o * PY + n] + bias[o])));
                const float v = r * Hsm[n * 65 + o];
                g_XT[5][(size_t)((o + 2) * 64 + b) * 1024 + n0 + n] = __float2half(v);
            }
        }
        {   // u -> g_u (o-coalesced)
            const int o = tid & 63;
            const int ng = tid >> 6;
            const float b1 = bias[o + 64];
#pragma unroll 1
            for (int w = 0; w < NTILE / 4; ++w) {
                const int n = ng + w * 4;
                const float u = 1.f / (1.f + expf(-(Ysm[(o + 64) * PY + n] + b1)));
                g_u[(size_t)b * 65536 + (size_t)(n0 + n) * 64 + o] = u;
            }
        }
    } else {
        __syncthreads();
        const int o = tid & 63;
        const int nb = tid >> 6;
        const float b0 = bias[o];
#pragma unroll 1
        for (int it = 0; it < NTILE / 4; ++it) {
            const int n = nb + it * 4;
            const size_t idx = (size_t)b * 65536 + (size_t)(n0 + n) * 64 + o;
            const float cc = tanhf(Ysm[o * PY + n] + b0);
            const float u = g_u[idx], h = hx[idx];
            outp[idx] = u * h + (1.f - u) * cc;
        }
    }
}

// ============================================================================
// Host driver
// ============================================================================
extern "C" void kernel_launch(void* const* d_in, const int* in_sizes, int n_in,
                              void* d_out, int out_size) {
    const float* inp = (const float*)d_in[0];
    const float* hx  = (const float*)d_in[1];
    const float* S0  = (const float*)d_in[2];
    const float* S1  = (const float*)d_in[3];
    const float* Wo  = (const float*)d_in[4];
    const float* bo  = (const float*)d_in[5];
    const float* Wu  = (const float*)d_in[6];
    const float* bu  = (const float*)d_in[7];
    float* out = (float*)d_out;

    auto* p1 = proj_mma<128, 128, 272, 272, 129, true>;
    auto* p2 = proj_mma<64, 256, 528, 144, 257, false>;
    const int P1_SMEM = 128 * 129 * 4 + 128 * 65 * 4;   // 99328 (> 4*8704)
    const int P2_SMEM = 64 * 257 * 4;                   // 65792 (> 4*10752)

    cudaFuncSetAttribute(gemm_mma<false>, cudaFuncAttributeMaxDynamicSharedMemorySize, DSMEM_BYTES);
    cudaFuncSetAttribute(gemm_mma<true>,  cudaFuncAttributeMaxDynamicSharedMemorySize, DSMEM_BYTES);
    cudaFuncSetAttribute(p1, cudaFuncAttributeMaxDynamicSharedMemorySize, P1_SMEM);
    cudaFuncSetAttribute(p2, cudaFuncAttributeMaxDynamicSharedMemorySize, P2_SMEM);

    __half *gWo = nullptr, *gWu = nullptr;
    cudaGetSymbolAddress((void**)&gWo, g_Wo16);
    cudaGetSymbolAddress((void**)&gWu, g_Wu16);

    pre_kernel<<<(PRE_TOTAL + 255) / 256, 256>>>(S0, S1, Wo, Wu, inp);
    build_h_kernel<<<dim3(16, 64), 256>>>(hx);

    const dim3 gG(NCOLS / NT, NNODES / MT, 2);   // (33, 8, 2)

    // pass 1 (X0 = slot 0)
    gemm_mma<false><<<gG, 256, DSMEM_BYTES>>>(0, 0, 1, 0);
    gemm_mma<true><<<gG, 256, DSMEM_BYTES>>>(1, 2, 2, 0);
    p1<<<dim3(8, 64), 256, P1_SMEM>>>(gWo, bo, hx, nullptr, 0);

    // pass 2 (X0 = slot 5, written by p1 + pre_kernel)
    gemm_mma<false><<<gG, 256, DSMEM_BYTES>>>(5, 0, 1, 5);
    gemm_mma<true><<<gG, 256, DSMEM_BYTES>>>(1, 2, 2, 5);
    p2<<<dim3(4, 64), 256, P2_SMEM>>>(gWu, bu, hx, out, 5);
}

// round 17
// speedup vs baseline: 1.5708x; 1.5708x over previous
#include <cuda_runtime.h>
#include <cuda_fp16.h>
#include <cstdint>
#include <math.h>

// ---------------- Problem constants ----------------
#define BDIM   64
#define NNODES 1024
#define UDIM   64
#define NCOLS  4224          // 66 features * 64 batch
#define NM     6             // slots: 0=X0(pass1), 1..4 diffusion, 5=X0(pass2)
#define XTSZ   (NCOLS * NNODES)

// Diffusion GEMM tiling (fp16 single term), KC=64, 2-stage R13 pipeline
#define MT 128
#define NT 128
#define KC 64
#define NCHUNK 16
#define ROWB 144             // 64 fp16 = 128B data + 16B pad (conflict-free ldmatrix)
#define REG_BYTES (128 * ROWB)        // 18432
#define OFF_A  0
#define OFF_B  (1 * REG_BYTES)
#define STAGE_BYTES (2 * REG_BYTES)   // 36864
#define DSMEM_BYTES (2 * STAGE_BYTES) // 73728 (>= epilogue 68096)

// ---------------- Device scratch ----------------
__device__ __align__(256) __half g_XT[NM][XTSZ];
__device__ __align__(256) __half g_S16[2][1024 * 1024];
__device__ __align__(256) __half g_Wo16[330 * 128];
__device__ __align__(256) __half g_Wu16[330 * 64];
__device__ __align__(256) float g_u[BDIM * NNODES * UDIM];

// ---------------- helpers ----------------
__device__ __forceinline__ uint32_t smem_u32(const void* p) {
    uint32_t a;
    asm("{ .reg .u64 t; cvta.to.shared.u64 t, %1; cvt.u32.u64 %0, t; }" : "=r"(a) : "l"(p));
    return a;
}
__device__ __forceinline__ void cp16(uint32_t saddr, const void* gaddr) {
    asm volatile("cp.async.cg.shared.global [%0], [%1], 16;" :: "r"(saddr), "l"(gaddr));
}
__device__ __forceinline__ void cp16z(uint32_t saddr, const void* gaddr, uint32_t srcsize) {
    asm volatile("cp.async.cg.shared.global [%0], [%1], 16, %2;"
                 :: "r"(saddr), "l"(gaddr), "r"(srcsize));
}
__device__ __forceinline__ void ldmx4a(uint32_t* r, uint32_t addr) {
    asm volatile("ldmatrix.sync.aligned.m8n8.x4.shared.b16 {%0,%1,%2,%3}, [%4];"
                 : "=r"(r[0]), "=r"(r[1]), "=r"(r[2]), "=r"(r[3]) : "r"(addr));
}
__device__ __forceinline__ void ldmx4t(uint32_t* r, uint32_t addr) {
    asm volatile("ldmatrix.sync.aligned.m8n8.x4.trans.shared.b16 {%0,%1,%2,%3}, [%4];"
                 : "=r"(r[0]), "=r"(r[1]), "=r"(r[2]), "=r"(r[3]) : "r"(addr));
}
__device__ __forceinline__ void mmaf16(float* c, const uint32_t* a, uint32_t b0, uint32_t b1) {
    asm volatile(
        "mma.sync.aligned.m16n8k16.row.col.f32.f16.f16.f32 "
        "{%0,%1,%2,%3}, {%4,%5,%6,%7}, {%8,%9}, {%0,%1,%2,%3};"
        : "+f"(c[0]), "+f"(c[1]), "+f"(c[2]), "+f"(c[3])
        : "r"(a[0]), "r"(a[1]), "r"(a[2]), "r"(a[3]), "r"(b0), "r"(b1));
}

// ============================================================================
// fused preprocessing: S -> fp16, W -> fp16, input rows -> slots 0 & 5
// ============================================================================
#define PRE_TOTAL (2097152 + 63360 + 131072)
__global__ void pre_kernel(const float* __restrict__ S0, const float* __restrict__ S1,
                           const float* __restrict__ Wo, const float* __restrict__ Wu,
                           const float* __restrict__ inp) {
    int idx = blockIdx.x * 256 + threadIdx.x;
    if (idx < 2097152) {
        int z = idx >> 20;
        int e = idx & 1048575;
        g_S16[z][e] = __float2half((z ? S1 : S0)[e]);
    } else if (idx < 2097152 + 63360) {
        int e = idx - 2097152;
        if (e < 42240) g_Wo16[e] = __float2half(Wo[e]);
        else           g_Wu16[e - 42240] = __float2half(Wu[e - 42240]);
    } else if (idx < PRE_TOTAL) {
        int e = idx - (2097152 + 63360);
        int c = e >> 10, i = e & 1023;
        int f = c >> 6, b = c & 63;
        __half h = __float2half(inp[b * 2048 + i * 2 + f]);
        g_XT[0][c * 1024 + i] = h;
        g_XT[5][c * 1024 + i] = h;
    }
}

// hidden rows from hx (pass 1) via smem transpose
__global__ __launch_bounds__(256)
void build_h_kernel(const float* __restrict__ hsrc) {
    __shared__ float T[64][65];
    const int i0 = blockIdx.x * 64;
    const int b  = blockIdx.y;
    const int tid = threadIdx.x;
    {
        const int u = tid & 63;
        const int iib = tid >> 6;
#pragma unroll
        for (int w = 0; w < 16; ++w) {
            const int ii = iib + w * 4;
            T[u][ii] = hsrc[(size_t)b * 65536 + (size_t)(i0 + ii) * 64 + u];
        }
    }
    __syncthreads();
    {
        const int ii = tid & 63;
        const int ub = tid >> 6;
#pragma unroll
        for (int w = 0; w < 16; ++w) {
            const int u = ub + w * 4;
            g_XT[0][(size_t)((u + 2) * 64 + b) * 1024 + i0 + ii] = __float2half(T[u][ii]);
        }
    }
}

// ============================================================================
// fp16 mma.sync diffusion GEMM: C = S[z] @ X[mi]  (CHEB: 2C - X0)
// grid (33, 8, 2), 256 threads. KC=64, 2-stage pipeline (R13 structure).
// ============================================================================
template <bool CHEB>
__global__ __launch_bounds__(256)
void gemm_mma(int inBase, int inStride, int outBase, int x0Idx) {
    const int z = blockIdx.z;
    const int it = blockIdx.y, jt = blockIdx.x;
    const int mi_idx = inBase + z * inStride;
    const int mo = outBase + 2 * z;

    const __half* __restrict__ Am = g_S16[z];
    const __half* __restrict__ Bm = g_XT[mi_idx];
    __half* __restrict__ Cm = g_XT[mo];
    const __half* __restrict__ X0 = g_XT[x0Idx];

    extern __shared__ char sm[];
    const uint32_t sb0 = smem_u32(sm);

    const int tid = threadIdx.x;
    const int warp = tid >> 5;
    const int lane = tid & 31;
    const int wm = warp >> 2;
    const int wn = warp & 3;

    const size_t arow0 = (size_t)(it * MT) * 1024;
    const size_t brow0 = (size_t)(jt * NT) * 1024;

    const uint32_t a_lm = (uint32_t)((lane & 15) * ROWB + ((lane >> 4) << 4));
    const uint32_t b_lm = (uint32_t)((((lane >> 4) << 3) + (lane & 7)) * ROWB +
                                     (((lane >> 3) & 1) << 4));

    float acc[4][4][4];
#pragma unroll
    for (int i = 0; i < 4; i++)
#pragma unroll
        for (int j = 0; j < 4; j++)
#pragma unroll
            for (int r = 0; r < 4; r++) acc[i][j][r] = 0.f;

    // stage loader: 2048 cp.async of 16B, 8 per thread
    auto issue = [&](int c) {
        const int buf = c & 1;
        const int k0 = c * KC;
        const uint32_t sbase = sb0 + buf * STAGE_BYTES;
#pragma unroll
        for (int q = 0; q < 8; q++) {
            int idx = tid + q * 256;
            int region = idx >> 10;            // 0..1
            int li = idx & 1023;
            int row = li >> 3;
            int seg = li & 7;
            const __half* gp = region ? (Bm + brow0) : (Am + arow0);
            gp += (size_t)row * 1024 + k0 + seg * 8;
            cp16(sbase + region * REG_BYTES + row * ROWB + seg * 16, gp);
        }
        asm volatile("cp.async.commit_group;" ::: "memory");
    };

    issue(0);

    for (int c = 0; c < NCHUNK; ++c) {
        if (c + 1 < NCHUNK) {
            issue(c + 1);
            asm volatile("cp.async.wait_group 1;" ::: "memory");
        } else {
            asm volatile("cp.async.wait_group 0;" ::: "memory");
        }
        __syncthreads();

        const uint32_t sbase = sb0 + (c & 1) * STAGE_BYTES;
        const uint32_t aB = sbase + a_lm + (uint32_t)(wm * 64) * ROWB;
        const uint32_t bB = sbase + b_lm + (uint32_t)(wn * 32) * ROWB;

        // preload ALL B fragments (4 k-steps)
        uint32_t bF[4][2][4];
#pragma unroll
        for (int s = 0; s < 4; ++s) {
            const uint32_t ks = (uint32_t)(s << 5);
#pragma unroll
            for (int p = 0; p < 2; ++p)
                ldmx4a(bF[s][p], bB + OFF_B + (uint32_t)(p * 16) * ROWB + ks);
        }
        // A ping-pong over 16 (s, mi) groups
        uint32_t aF[2][4];
        ldmx4a(aF[0], aB + OFF_A);
#pragma unroll
        for (int g = 0; g < 16; ++g) {
            const int s = g >> 2, mi = g & 3;
            const int cur = g & 1;
            if (g < 15) {
                const int g2 = g + 1;
                const uint32_t ao = (uint32_t)((g2 & 3) * 16) * ROWB +
                                    (uint32_t)((g2 >> 2) << 5);
                ldmx4a(aF[cur ^ 1], aB + OFF_A + ao);
            }
#pragma unroll
            for (int nj = 0; nj < 4; ++nj) {
                const int p = nj >> 1, h = (nj & 1) << 1;
                mmaf16(acc[mi][nj], aF[cur], bF[s][p][h], bF[s][p][h + 1]);
            }
        }
        __syncthreads();
    }

    // epilogue: stride-133 smem transpose; scalar stores (odd stride, 8B traps)
    float* Csm = (float*)sm;
    const int gid = lane >> 2;
    const int tig = lane & 3;
#pragma unroll
    for (int mi = 0; mi < 4; ++mi) {
#pragma unroll
        for (int nj = 0; nj < 4; ++nj) {
            const int r0 = wm * 64 + mi * 16 + gid;
            const int n = wn * 32 + nj * 8 + 2 * tig;
            Csm[r0 * 133 + n]           = acc[mi][nj][0];
            Csm[r0 * 133 + n + 1]       = acc[mi][nj][1];
            Csm[(r0 + 8) * 133 + n]     = acc[mi][nj][2];
            Csm[(r0 + 8) * 133 + n + 1] = acc[mi][nj][3];
        }
    }
    __syncthreads();

#pragma unroll 1
    for (int iter = 0; iter < 16; ++iter) {
        const int j = iter * 8 + warp;
        const size_t jg = (size_t)(jt * NT + j);
#pragma unroll
        for (int q = 0; q < 4; ++q) {
            const int i = lane + q * 32;
            const size_t ig = (size_t)(it * MT) + i;
            float y = Csm[i * 133 + j];
            if (CHEB)
                y = 2.f * y - __half2float(X0[jg * 1024 + ig]);
            Cm[jg * 1024 + ig] = __float2half(y);
        }
    }
}

// ============================================================================
// Tensor-core projection (fp16 single-term). K=330 padded to 336.
// 2-stage pipeline (R13 structure).
// IS_P1: r -> XT slot 5 hidden rows fused, u -> g_u.
// else : c = tanh(.), out = u*hx + (1-u)*c.
// ============================================================================
template <int OUT, int NTILE, int PX, int PW, int PY, bool IS_P1>
__global__ __launch_bounds__(256)
void proj_mma(const __half* __restrict__ Wm, const float* __restrict__ bias,
              const float* __restrict__ hx, float* __restrict__ outp, int x0slot) {
    constexpr int XSEG = NTILE / 8;
    constexpr int WSEG = OUT / 8;
    constexpr int OFF_X = 0;
    constexpr int OFF_W = 16 * PX;
    constexpr int STAGE = 16 * PX + 16 * PW;
    constexpr int TOTAL = 2 * NTILE + 2 * OUT;
    constexpr int NQ = (TOTAL + 255) / 256;
    constexpr int NCK = 21;
    constexpr int WN_CNT = NTILE / 32;

    const int n0 = blockIdx.x * NTILE;
    const int b  = blockIdx.y;

    extern __shared__ char sm[];
    const uint32_t sb0 = smem_u32(sm);

    const int tid = threadIdx.x;
    const int warp = tid >> 5;
    const int lane = tid & 31;
    const int wm = warp / WN_CNT;
    const int wn = warp % WN_CNT;

    const uint32_t a_lmT = (uint32_t)(((lane & 7) + ((lane >> 4) & 1) * 8) * PW +
                                      (((lane >> 3) & 1) << 4));
    const uint32_t b_lmT = (uint32_t)(((lane & 7) + ((lane >> 3) & 1) * 8) * PX +
                                      ((lane >> 4) << 4));

    float acc[4][4][4];
#pragma unroll
    for (int i = 0; i < 4; i++)
#pragma unroll
        for (int j = 0; j < 4; j++)
#pragma unroll
            for (int r = 0; r < 4; r++) acc[i][j][r] = 0.f;

    const __half* X0 = &g_XT[0][0];

    auto issue = [&](int c) {
        const uint32_t sbase = sb0 + (c & 1) * STAGE;
        const int k0 = c * 16;
#pragma unroll
        for (int q = 0; q < NQ; q++) {
            int idx = tid + q * 256;
            if (idx >= TOTAL) break;
            if (idx < 2 * NTILE) {
                const int row = idx / XSEG, seg = idx % XSEG;
                const int k = k0 + row;
                const uint32_t sz = (k < 330) ? 16u : 0u;
                const int kk = (k < 330) ? k : 0;
                const int f = kk / 5, m = kk - f * 5;
                const int mslot = (m == 0) ? x0slot : m;
                const __half* src = X0 + (size_t)mslot * XTSZ +
                                    (size_t)(f * 64 + b) * 1024 + n0 + seg * 8;
                cp16z(sbase + OFF_X + row * PX + seg * 16, src, sz);
            } else {
                const int li = idx - 2 * NTILE;
                const int row = li / WSEG, seg = li % WSEG;
                const int k = k0 + row;
                const uint32_t sz = (k < 330) ? 16u : 0u;
                const int kk = (k < 330) ? k : 0;
                cp16z(sbase + OFF_W + row * PW + seg * 16, Wm + kk * OUT + seg * 8, sz);
            }
        }
        asm volatile("cp.async.commit_group;" ::: "memory");
    };

    issue(0);

    for (int c = 0; c < NCK; ++c) {
        if (c + 1 < NCK) {
            issue(c + 1);
            asm volatile("cp.async.wait_group 1;" ::: "memory");
        } else {
            asm volatile("cp.async.wait_group 0;" ::: "memory");
        }
        __syncthreads();

        const uint32_t sbase = sb0 + (c & 1) * STAGE;
        uint32_t bF[2][4];
#pragma unroll
        for (int p = 0; p < 2; ++p)
            ldmx4t(bF[p], sbase + OFF_X + b_lmT + (uint32_t)((wn * 32 + p * 16) * 2));
#pragma unroll
        for (int mi = 0; mi < 4; ++mi) {
            uint32_t aw[4];
            ldmx4t(aw, sbase + OFF_W + a_lmT + (uint32_t)((wm * 64 + mi * 16) * 2));
#pragma unroll
            for (int nj = 0; nj < 4; ++nj) {
                const int p = nj >> 1, h = (nj & 1) << 1;
                mmaf16(acc[mi][nj], aw, bF[p][h], bF[p][h + 1]);
            }
        }
        __syncthreads();
    }

    // stage Y^T[o][n] in smem (odd pitch PY; scalar stores)
    float* Ysm = (float*)sm;
    const int gid = lane >> 2;
    const int tig = lane & 3;
#pragma unroll
    for (int mi = 0; mi < 4; ++mi) {
#pragma unroll
        for (int nj = 0; nj < 4; ++nj) {
            const int o0 = wm * 64 + mi * 16 + gid;
            const int n = wn * 32 + nj * 8 + 2 * tig;
            Ysm[o0 * PY + n]           = acc[mi][nj][0];
            Ysm[o0 * PY + n + 1]       = acc[mi][nj][1];
            Ysm[(o0 + 8) * PY + n]     = acc[mi][nj][2];
            Ysm[(o0 + 8) * PY + n + 1] = acc[mi][nj][3];
        }
    }

    if (IS_P1) {
        float* Hsm = (float*)(sm + OUT * PY * 4);
        {
            const int o = tid & 63;
            const int ng = tid >> 6;
#pragma unroll
            for (int w = 0; w < NTILE / 4; ++w) {
                const int n = ng + w * 4;
                Hsm[n * 65 + o] = hx[(size_t)b * 65536 + (size_t)(n0 + n) * 64 + o];
            }
        }
        __syncthreads();
        {   // rh = sigmoid(Y + b0) * hx -> XT slot 5 (n-coalesced)
            const int n = tid & 127;
            const int og = tid >> 7;
#pragma unroll 1
            for (int ow = 0; ow < 32; ++ow) {
                const int o = og * 32 + ow;
                const float r = 1.f / (1.f + expf(-(Ysm[o * PY + n] + bias[o])));
                const float v = r * Hsm[n * 65 + o];
                g_XT[5][(size_t)((o + 2) * 64 + b) * 1024 + n0 + n] = __float2half(v);
            }
        }
        {   // u -> g_u (o-coalesced)
            const int o = tid & 63;
            const int ng = tid >> 6;
            const float b1 = bias[o + 64];
#pragma unroll 1
            for (int w = 0; w < NTILE / 4; ++w) {
                const int n = ng + w * 4;
                const float u = 1.f / (1.f + expf(-(Ysm[(o + 64) * PY + n] + b1)));
                g_u[(size_t)b * 65536 + (size_t)(n0 + n) * 64 + o] = u;
            }
        }
    } else {
        __syncthreads();
        const int o = tid & 63;
        const int nb = tid >> 6;
        const float b0 = bias[o];
#pragma unroll 1
        for (int it = 0; it < NTILE / 4; ++it) {
            const int n = nb + it * 4;
            const size_t idx = (size_t)b * 65536 + (size_t)(n0 + n) * 64 + o;
            const float cc = tanhf(Ysm[o * PY + n] + b0);
            const float u = g_u[idx], h = hx[idx];
            outp[idx] = u * h + (1.f - u) * cc;
        }
    }
}

// ============================================================================
// Host driver
// ============================================================================
extern "C" void kernel_launch(void* const* d_in, const int* in_sizes, int n_in,
                              void* d_out, int out_size) {
    const float* inp = (const float*)d_in[0];
    const float* hx  = (const float*)d_in[1];
    const float* S0  = (const float*)d_in[2];
    const float* S1  = (const float*)d_in[3];
    const float* Wo  = (const float*)d_in[4];
    const float* bo  = (const float*)d_in[5];
    const float* Wu  = (const float*)d_in[6];
    const float* bu  = (const float*)d_in[7];
    float* out = (float*)d_out;

    auto* p1 = proj_mma<128, 128, 272, 272, 129, true>;
    auto* p2 = proj_mma<64, 256, 528, 144, 257, false>;
    const int P1_SMEM = 128 * 129 * 4 + 128 * 65 * 4;   // 99328 (> 2*8704)
    const int P2_SMEM = 64 * 257 * 4;                   // 65792 (> 2*10752)

    cudaFuncSetAttribute(gemm_mma<false>, cudaFuncAttributeMaxDynamicSharedMemorySize, DSMEM_BYTES);
    cudaFuncSetAttribute(gemm_mma<true>,  cudaFuncAttributeMaxDynamicSharedMemorySize, DSMEM_BYTES);
    cudaFuncSetAttribute(p1, cudaFuncAttributeMaxDynamicSharedMemorySize, P1_SMEM);
    cudaFuncSetAttribute(p2, cudaFuncAttributeMaxDynamicSharedMemorySize, P2_SMEM);

    __half *gWo = nullptr, *gWu = nullptr;
    cudaGetSymbolAddress((void**)&gWo, g_Wo16);
    cudaGetSymbolAddress((void**)&gWu, g_Wu16);

    pre_kernel<<<(PRE_TOTAL + 255) / 256, 256>>>(S0, S1, Wo, Wu, inp);
    build_h_kernel<<<dim3(16, 64), 256>>>(hx);

    const dim3 gG(NCOLS / NT, NNODES / MT, 2);   // (33, 8, 2)

    // pass 1 (X0 = slot 0)
    gemm_mma<false><<<gG, 256, DSMEM_BYTES>>>(0, 0, 1, 0);
    gemm_mma<true><<<gG, 256, DSMEM_BYTES>>>(1, 2, 2, 0);
    p1<<<dim3(8, 64), 256, P1_SMEM>>>(gWo, bo, hx, nullptr, 0);

    // pass 2 (X0 = slot 5, written by p1 + pre_kernel)
    gemm_mma<false><<<gG, 256, DSMEM_BYTES>>>(5, 0, 1, 5);
    gemm_mma<true><<<gG, 256, DSMEM_BYTES>>>(1, 2, 2, 5);
    p2<<<dim3(4, 64), 256, P2_SMEM>>>(gWu, bu, hx, out, 5);
}